// round 1
// baseline (speedup 1.0000x reference)
#include <cuda_runtime.h>
#include <math.h>

#define NDIRS 5
#define NE    16
#define NW    3
#define ND    128
#define NP    256
#define NB    4
#define WK    768   // NW*NP
#define MT    64    // rows per block
#define KT    32    // k-tile

struct RoutesP { int ve[NE][NW]; };

// ---- packed f32x2 helpers (Blackwell) ----
__device__ __forceinline__ unsigned long long pack2(float a, float b){
    unsigned long long r;
    asm("mov.b64 %0, {%1, %2};" : "=l"(r) : "f"(a), "f"(b));
    return r;
}
__device__ __forceinline__ unsigned long long dup2(float a){
    unsigned long long r;
    asm("mov.b64 %0, {%1, %1};" : "=l"(r) : "f"(a));
    return r;
}
__device__ __forceinline__ void unpack2(unsigned long long v, float& a, float& b){
    asm("mov.b64 {%0, %1}, %2;" : "=f"(a), "=f"(b) : "l"(v));
}
__device__ __forceinline__ void ffma2(unsigned long long& d, unsigned long long a, unsigned long long b){
    asm("fma.rn.f32x2 %0, %1, %2, %0;" : "+l"(d) : "l"(a), "l"(b));
}

__global__ __launch_bounds__(256, 1)
void cantor_attn_kernel(const float* __restrict__ Q,
                        const float* __restrict__ Kf,
                        const float* __restrict__ V,
                        const float* __restrict__ betas,
                        const float* __restrict__ temp,
                        const float* __restrict__ fw,
                        float* __restrict__ out,
                        RoutesP rp)
{
    __shared__ float sS[WK];            // scaled K row (s vector)
    __shared__ float sV[KT][ND];        // V tile
    __shared__ float sE[MT][KT + 1];    // scaled exp tile (padded)
    __shared__ float sQ[MT];
    __shared__ float sMx[MT];
    __shared__ float sScale[MT];        // w_x / den_r
    __shared__ float sRed[256];
    __shared__ float sMM[2];            // smax, smin

    const int tid = threadIdx.x;
    const int e  = blockIdx.z;
    const int b  = blockIdx.y;
    const int m0 = blockIdx.x * MT;

    const float invtemp = 1.0f / (fabsf(temp[0]) + 1e-6f);

    // fusion softmax weights (tiny, redundant per thread)
    float fwv[NDIRS];
    float fm = -1e30f;
    #pragma unroll
    for (int x = 0; x < NDIRS; x++){ fwv[x] = fw[x]; fm = fmaxf(fm, fwv[x]); }
    float fsum = 0.0f;
    #pragma unroll
    for (int x = 0; x < NDIRS; x++){ fwv[x] = __expf(fwv[x] - fm); fsum += fwv[x]; }
    const float finv = 1.0f / fsum;

    // routes + beta factors (x-independent)
    int   ve[NW];
    float bfw[NW];
    #pragma unroll
    for (int w = 0; w < NW; w++){
        int r = rp.ve[e][w];
        ve[w] = r;
        float bf = (r == e) ? 1.0f : 1.0f / (1.0f + __expf(-betas[e * NE + r]));
        bfw[w] = bf * invtemp;
    }

    // accumulators: 8 rows x 4 cols = 16 f32x2
    unsigned long long acc[16];
    #pragma unroll
    for (int i = 0; i < 16; i++) acc[i] = dup2(0.0f);

    const int r_den = tid & 63;          // row for exp/den phases
    const int part  = tid >> 6;          // 0..3
    const int ty    = tid >> 5;          // warp id 0..7
    const int tx    = tid & 31;
    const int r0    = ty * 8;            // 8 rows per thread
    const int c0    = tx * 4;            // 4 cols per thread
    const int lane  = tid & 31;

    for (int x = 0; x < NDIRS; x++){
        const float wx = fwv[x] * finv;

        // --- load s (gathered, scaled K) and q rows ---
        for (int idx = tid; idx < WK; idx += 256){
            int w = idx >> 8, k = idx & 255;
            sS[idx] = Kf[(((x * NE + ve[w]) * NB + b) << 8) + k] * bfw[w];
        }
        if (tid < MT)
            sQ[tid] = Q[(((x * NE + e) * NB + b) << 8) + m0 + tid];
        __syncthreads();

        // --- min/max of s (exact row max is q*smax or q*smin) ---
        float lmax = -1e30f, lmin = 1e30f;
        #pragma unroll
        for (int i = 0; i < 3; i++){
            float v = sS[tid + i * 256];
            lmax = fmaxf(lmax, v); lmin = fminf(lmin, v);
        }
        #pragma unroll
        for (int off = 16; off; off >>= 1){
            lmax = fmaxf(lmax, __shfl_xor_sync(0xffffffffu, lmax, off));
            lmin = fminf(lmin, __shfl_xor_sync(0xffffffffu, lmin, off));
        }
        if (lane == 0){ sRed[ty] = lmax; sRed[8 + ty] = lmin; }
        __syncthreads();
        if (tid == 0){
            float a = -1e30f, c = 1e30f;
            #pragma unroll
            for (int i = 0; i < 8; i++){ a = fmaxf(a, sRed[i]); c = fminf(c, sRed[8 + i]); }
            sMM[0] = a; sMM[1] = c;
        }
        __syncthreads();
        if (tid < MT){
            float q = sQ[tid];
            sMx[tid] = fmaxf(q * sMM[0], q * sMM[1]);
        }
        __syncthreads();

        // --- denominator pass ---
        {
            float q = sQ[r_den], mx = sMx[r_den], loc = 0.0f;
            for (int k = part; k < WK; k += 4)
                loc += __expf(__fmaf_rn(q, sS[k], -mx));
            sRed[tid] = loc;
        }
        __syncthreads();
        if (tid < MT){
            float den = sRed[tid] + sRed[64 + tid] + sRed[128 + tid] + sRed[192 + tid];
            sScale[tid] = wx / den;   // fold fusion weight + 1/den into exp tile
        }
        __syncthreads();

        // --- main k-tiled GEMM: acc += (scale_r * exp(q_r*s_k - mx_r)) * V[k, :] ---
        for (int kt = 0; kt < WK; kt += KT){
            int w = kt >> 8;  // KT divides NP, tile never crosses w boundary
            const float4* vg4 = (const float4*)(V +
                ((((size_t)(x * NE + ve[w]) * NB + b) << 8) + (size_t)(kt & 255)) * ND);
            #pragma unroll
            for (int i = 0; i < 4; i++){
                int lin = tid + i * 256;       // 0..1023 float4 slots
                int row = lin >> 5, col = lin & 31;
                ((float4*)&sV[row][0])[col] = vg4[row * 32 + col];
            }
            {
                float q = sQ[r_den], mx = sMx[r_den], sc = sScale[r_den];
                int kb = part * 8;
                #pragma unroll
                for (int j = 0; j < 8; j++)
                    sE[r_den][kb + j] = __expf(__fmaf_rn(q, sS[kt + kb + j], -mx)) * sc;
            }
            __syncthreads();

            #pragma unroll 4
            for (int kk = 0; kk < KT; kk++){
                float4 v = *(const float4*)&sV[kk][c0];
                unsigned long long v01 = pack2(v.x, v.y);
                unsigned long long v23 = pack2(v.z, v.w);
                #pragma unroll
                for (int i = 0; i < 8; i++){
                    unsigned long long ee = dup2(sE[r0 + i][kk]);  // broadcast LDS
                    ffma2(acc[2 * i],     ee, v01);
                    ffma2(acc[2 * i + 1], ee, v23);
                }
            }
            __syncthreads();
        }
    }

    // --- write output: out[b][e*NP + p][d], fp32 ---
    float* op = out + ((size_t)b * (NE * NP) + (size_t)e * NP + m0 + r0) * ND + c0;
    #pragma unroll
    for (int i = 0; i < 8; i++){
        float4 o;
        unpack2(acc[2 * i],     o.x, o.y);
        unpack2(acc[2 * i + 1], o.z, o.w);
        *(float4*)(op + (size_t)i * ND) = o;
    }
}

// ---- host: replicate numpy route construction exactly ----
// cantor coord computed in DOUBLE (python floats), cast to float32 at the end;
// distances in float32; stable argsort (ties -> lower index); top-3 sorted.
static void compute_routes(RoutesP* rp)
{
    float coords[NE];
    for (int i = 0; i < NE; i++){
        double xx = (double)i / 15.0;
        if (xx < 1e-6)       xx = 1e-6;
        if (xx > 1.0 - 1e-6) xx = 1.0 - 1e-6;
        double val = 0.0, f = 0.5;
        for (int d = 0; d < 8; d++){
            xx *= 3.0;
            int dig = (int)xx;
            xx -= (double)dig;
            if (dig == 2) val += f;
            f *= 0.5;
        }
        coords[i] = (float)val;
    }
    for (int i = 0; i < NE; i++){
        float dist[NE]; int idx[NE];
        for (int j = 0; j < NE; j++){
            dist[j] = fabsf(coords[j] - coords[i]);
            idx[j]  = j;
        }
        // stable insertion sort by distance
        for (int a = 1; a < NE; a++){
            float dv = dist[a]; int iv = idx[a];
            int c = a - 1;
            while (c >= 0 && dist[c] > dv){
                dist[c + 1] = dist[c]; idx[c + 1] = idx[c]; c--;
            }
            dist[c + 1] = dv; idx[c + 1] = iv;
        }
        int r3[NW] = { idx[0], idx[1], idx[2] };
        // sort the 3 route indices ascending
        for (int a = 0; a < NW; a++)
            for (int c = a + 1; c < NW; c++)
                if (r3[c] < r3[a]){ int t = r3[a]; r3[a] = r3[c]; r3[c] = t; }
        for (int w = 0; w < NW; w++) rp->ve[i][w] = r3[w];
    }
}

extern "C" void kernel_launch(void* const* d_in, const int* in_sizes, int n_in,
                              void* d_out, int out_size)
{
    (void)in_sizes; (void)n_in; (void)out_size;
    RoutesP rp;
    compute_routes(&rp);

    dim3 grid(NP / MT, NB, NE);   // 4 x 4 x 16 = 256 blocks
    dim3 block(256);
    cantor_attn_kernel<<<grid, block>>>(
        (const float*)d_in[0],   // Q_aff
        (const float*)d_in[1],   // K_aff
        (const float*)d_in[2],   // V
        (const float*)d_in[3],   // betas
        (const float*)d_in[4],   // temperature
        (const float*)d_in[5],   // fusion_weights
        (float*)d_out, rp);
}

// round 4
// speedup vs baseline: 3.0388x; 3.0388x over previous
#include <cuda_runtime.h>
#include <cuda_bf16.h>
#include <math.h>
#include <stdint.h>

#define NDIRS 5
#define NE    16
#define NW    3
#define ND    128
#define NP    256
#define NB    4
#define WK    768
#define MT    128
#define KC    64
#define NCH   (WK/KC)   // 12 chunks per x
#define LOG2E 1.4426950408889634f

struct RoutesP { int ve[NE][NW]; };

// V split planes, [x][e][b][p][d], bf16 hi/lo (elementwise, same layout as V)
__device__ __align__(16) __nv_bfloat16 g_vh[(size_t)NDIRS*NE*NB*NP*ND];
__device__ __align__(16) __nv_bfloat16 g_vl[(size_t)NDIRS*NE*NB*NP*ND];

// ---------------- dynamic smem layout ----------------
// stage s: hi tile [KC][128] bf16 (16KB) + lo tile (16KB), XOR-swizzled 16B chunks
#define SM_HI(s)  ((s)*32768)
#define SM_LO(s)  ((s)*32768 + 16384)
#define SM_S      65536                // f32[768]
#define SM_Q      (SM_S + 3072)       // f32[128]
#define SM_MX     (SM_Q + 512)        // f32[128]
#define SM_RED    (SM_MX + 512)       // f32[16]
#define SM_MM     (SM_RED + 64)       // f32[2]
#define SMEM_TOTAL (SM_MM + 64)

// ---------------- helpers ----------------
__device__ __forceinline__ uint32_t smem_u32(const void* p){
    uint32_t a;
    asm("{ .reg .u64 t; cvta.to.shared.u64 t, %1; cvt.u32.u64 %0, t; }" : "=r"(a) : "l"(p));
    return a;
}
__device__ __forceinline__ float ex2f(float x){
    float r; asm("ex2.approx.ftz.f32 %0, %1;" : "=f"(r) : "f"(x)); return r;
}
// bf16x2: low half = a, high half = b
__device__ __forceinline__ uint32_t pack_bf(float a, float b){
    uint32_t r;
    asm("cvt.rn.bf16x2.f32 %0, %1, %2;" : "=r"(r) : "f"(b), "f"(a));
    return r;
}
__device__ __forceinline__ void ldsm4t(uint32_t& r0, uint32_t& r1, uint32_t& r2, uint32_t& r3,
                                       uint32_t addr){
    asm volatile("ldmatrix.sync.aligned.m8n8.x4.trans.shared.b16 {%0,%1,%2,%3}, [%4];"
                 : "=r"(r0), "=r"(r1), "=r"(r2), "=r"(r3) : "r"(addr));
}
__device__ __forceinline__ void mma16816(float* c,
                                         uint32_t a0, uint32_t a1, uint32_t a2, uint32_t a3,
                                         uint32_t b0, uint32_t b1){
    asm volatile("mma.sync.aligned.m16n8k16.row.col.f32.bf16.bf16.f32 "
                 "{%0,%1,%2,%3}, {%4,%5,%6,%7}, {%8,%9}, {%0,%1,%2,%3};"
                 : "+f"(c[0]), "+f"(c[1]), "+f"(c[2]), "+f"(c[3])
                 : "r"(a0), "r"(a1), "r"(a2), "r"(a3), "r"(b0), "r"(b1));
}
__device__ __forceinline__ void cp16(uint32_t dst, const void* src){
    asm volatile("cp.async.cg.shared.global [%0], [%1], 16;" :: "r"(dst), "l"(src));
}
__device__ __forceinline__ void cp_commit(){ asm volatile("cp.async.commit_group;" ::: "memory"); }
template<int N> __device__ __forceinline__ void cp_wait(){
    asm volatile("cp.async.wait_group %0;" :: "n"(N) : "memory");
}

// stage a KC x 128 hi/lo chunk into smem with 16B-chunk XOR swizzle
__device__ __forceinline__ void issue_chunk(uint32_t smb, int st,
                                            const __nv_bfloat16* __restrict__ srcH,
                                            const __nv_bfloat16* __restrict__ srcL,
                                            int tid){
    #pragma unroll
    for (int i = 0; i < 4; i++){
        int cid = tid + i * 256;              // 0..1023 16B chunks
        int row = cid >> 4, c = cid & 15;
        uint32_t soff = (uint32_t)(row * 256 + ((c ^ (row & 7)) << 4));
        cp16(smb + SM_HI(st) + soff, srcH + row * ND + c * 8);
        cp16(smb + SM_LO(st) + soff, srcL + row * ND + c * 8);
    }
}

// ---------------- pre-kernel: elementwise V -> bf16 hi/lo ----------------
__global__ __launch_bounds__(256)
void vsplit_kernel(const float* __restrict__ V){
    size_t i = ((size_t)blockIdx.x * 256 + threadIdx.x) * 4;
    float4 v = *(const float4*)(V + i);
    uint32_t h0 = pack_bf(v.x, v.y);
    uint32_t h1 = pack_bf(v.z, v.w);
    float fx = __uint_as_float(h0 << 16),        fy = __uint_as_float(h0 & 0xFFFF0000u);
    float fz = __uint_as_float(h1 << 16),        fw = __uint_as_float(h1 & 0xFFFF0000u);
    uint32_t l0 = pack_bf(v.x - fx, v.y - fy);
    uint32_t l1 = pack_bf(v.z - fz, v.w - fw);
    uint2 ph = {h0, h1}, pl = {l0, l1};
    *(uint2*)((char*)g_vh + i * 2) = ph;
    *(uint2*)((char*)g_vl + i * 2) = pl;
}

// ---------------- main kernel ----------------
__global__ __launch_bounds__(256, 1)
void cantor_attn_mma(const float* __restrict__ Q,
                     const float* __restrict__ Kf,
                     const float* __restrict__ betas,
                     const float* __restrict__ temp,
                     const float* __restrict__ fw,
                     float* __restrict__ out,
                     RoutesP rp)
{
    extern __shared__ char sm[];
    const uint32_t smb = smem_u32(sm);
    float* sS  = (float*)(sm + SM_S);
    float* sQ  = (float*)(sm + SM_Q);
    float* sMx = (float*)(sm + SM_MX);
    float* sRed= (float*)(sm + SM_RED);
    float* sMM = (float*)(sm + SM_MM);

    const int tid  = threadIdx.x;
    const int lane = tid & 31;
    const int wid  = tid >> 5;
    const int wm   = wid & 3;          // m-group: rows wm*32..+31
    const int wn   = wid >> 2;         // n-half: cols wn*64..+63
    const int e  = blockIdx.z;
    const int b  = blockIdx.y;
    const int m0 = blockIdx.x * MT;

    const float invtemp = 1.0f / (fabsf(temp[0]) + 1e-6f);

    // fusion softmax weights
    float fwv[NDIRS], fm = -1e30f;
    #pragma unroll
    for (int x = 0; x < NDIRS; x++){ fwv[x] = fw[x]; fm = fmaxf(fm, fwv[x]); }
    float fsum = 0.0f;
    #pragma unroll
    for (int x = 0; x < NDIRS; x++){ fwv[x] = __expf(fwv[x] - fm); fsum += fwv[x]; }
    const float finv = 1.0f / fsum;

    int   ve[NW]; float bfw[NW];
    #pragma unroll
    for (int w = 0; w < NW; w++){
        int r = rp.ve[e][w];
        ve[w] = r;
        float bf = (r == e) ? 1.0f : 1.0f / (1.0f + __expf(-betas[e * NE + r]));
        bfw[w] = bf * invtemp;
    }

    float cT[16][4];
    #pragma unroll
    for (int f = 0; f < 16; f++){
        cT[f][0] = 0.f; cT[f][1] = 0.f; cT[f][2] = 0.f; cT[f][3] = 0.f;
    }

    const int c0   = (lane & 3) * 2;
    const int r0l  = wm * 32 + (lane >> 2);

    for (int x = 0; x < NDIRS; x++){
        __syncthreads();   // previous x fully done with sS + stage0

        // prefetch chunk 0 (overlaps prologue)
        {
            const size_t pb = (size_t)((x * NE + ve[0]) * NB + b) * (NP * ND);
            issue_chunk(smb, 0, g_vh + pb, g_vl + pb, tid);
            cp_commit();
        }

        // ---- prologue: s, q, minmax, mx ----
        #pragma unroll
        for (int i = 0; i < 3; i++){
            int idx = tid + i * 256;
            int w = idx >> 8, k = idx & 255;
            sS[idx] = Kf[(((x * NE + ve[w]) * NB + b) << 8) + k] * bfw[w];
        }
        if (tid < MT)
            sQ[tid] = Q[(((x * NE + e) * NB + b) << 8) + m0 + tid];
        __syncthreads();

        float lmax = -1e30f, lmin = 1e30f;
        #pragma unroll
        for (int i = 0; i < 3; i++){
            float v = sS[tid + i * 256];
            lmax = fmaxf(lmax, v); lmin = fminf(lmin, v);
        }
        #pragma unroll
        for (int off = 16; off; off >>= 1){
            lmax = fmaxf(lmax, __shfl_xor_sync(0xffffffffu, lmax, off));
            lmin = fminf(lmin, __shfl_xor_sync(0xffffffffu, lmin, off));
        }
        if (lane == 0){ sRed[wid] = lmax; sRed[8 + wid] = lmin; }
        __syncthreads();
        if (tid == 0){
            float a = -1e30f, c = 1e30f;
            #pragma unroll
            for (int i = 0; i < 8; i++){ a = fmaxf(a, sRed[i]); c = fminf(c, sRed[8 + i]); }
            sMM[0] = a; sMM[1] = c;
        }
        __syncthreads();
        if (tid < MT){
            float q = sQ[tid];
            sMx[tid] = fmaxf(q * sMM[0], q * sMM[1]);
        }
        __syncthreads();

        // per-thread row constants (rows r0l + 8j), log2e folded
        float q2[4], mxn2[4];
        #pragma unroll
        for (int j = 0; j < 4; j++){
            q2[j]   = sQ[r0l + 8 * j] * LOG2E;
            mxn2[j] = -sMx[r0l + 8 * j] * LOG2E;
        }

        float cX[16][4];
        #pragma unroll
        for (int f = 0; f < 16; f++){
            cX[f][0] = 0.f; cX[f][1] = 0.f; cX[f][2] = 0.f; cX[f][3] = 0.f;
        }
        float den[4] = {0.f, 0.f, 0.f, 0.f};

        // ---- chunk loop ----
        for (int ch = 0; ch < NCH; ch++){
            if (ch > 0) __syncthreads();          // stage (ch+1)&1 free before overwrite
            if (ch + 1 < NCH){
                int kt = (ch + 1) * KC;
                const size_t pb = (size_t)((x * NE + ve[kt >> 8]) * NB + b) * (NP * ND)
                                  + (size_t)(kt & 255) * ND;
                issue_chunk(smb, (ch + 1) & 1, g_vh + pb, g_vl + pb, tid);
                cp_commit();
                cp_wait<1>();
            } else {
                cp_wait<0>();
            }
            __syncthreads();

            const int st = ch & 1;
            const int koff = ch * KC;

            #pragma unroll
            for (int k16 = 0; k16 < 4; k16++){
                const int kb = k16 * 16;

                // ---- A fragments: exp at fragment coords, hi/lo split ----
                float sv0 = sS[koff + kb + c0];
                float sv1 = sS[koff + kb + c0 + 1];
                float sv2 = sS[koff + kb + c0 + 8];
                float sv3 = sS[koff + kb + c0 + 9];

                uint32_t ah[2][4], al[2][4];
                #pragma unroll
                for (int mt = 0; mt < 2; mt++){
                    float qa = q2[2 * mt],     ma = mxn2[2 * mt];
                    float qb = q2[2 * mt + 1], mb = mxn2[2 * mt + 1];
                    float ea0 = ex2f(fmaf(qa, sv0, ma));
                    float ea1 = ex2f(fmaf(qa, sv1, ma));
                    float ea2 = ex2f(fmaf(qa, sv2, ma));
                    float ea3 = ex2f(fmaf(qa, sv3, ma));
                    float eb0 = ex2f(fmaf(qb, sv0, mb));
                    float eb1 = ex2f(fmaf(qb, sv1, mb));
                    float eb2 = ex2f(fmaf(qb, sv2, mb));
                    float eb3 = ex2f(fmaf(qb, sv3, mb));
                    den[2 * mt]     += (ea0 + ea1) + (ea2 + ea3);
                    den[2 * mt + 1] += (eb0 + eb1) + (eb2 + eb3);

                    uint32_t h;
                    h = pack_bf(ea0, ea1); ah[mt][0] = h;
                    al[mt][0] = pack_bf(ea0 - __uint_as_float(h << 16),
                                        ea1 - __uint_as_float(h & 0xFFFF0000u));
                    h = pack_bf(eb0, eb1); ah[mt][1] = h;
                    al[mt][1] = pack_bf(eb0 - __uint_as_float(h << 16),
                                        eb1 - __uint_as_float(h & 0xFFFF0000u));
                    h = pack_bf(ea2, ea3); ah[mt][2] = h;
                    al[mt][2] = pack_bf(ea2 - __uint_as_float(h << 16),
                                        ea3 - __uint_as_float(h & 0xFFFF0000u));
                    h = pack_bf(eb2, eb3); ah[mt][3] = h;
                    al[mt][3] = pack_bf(eb2 - __uint_as_float(h << 16),
                                        eb3 - __uint_as_float(h & 0xFFFF0000u));
                }

                // ---- B fragments + MMA, 4 n-tile pairs (cols wn*64 + p*16) ----
                const int m8 = lane >> 3, w8 = lane & 7;
                const int kr = kb + (m8 & 1) * 8 + w8;          // row in chunk
                #pragma unroll
                for (int p = 0; p < 4; p++){
                    const int cc = wn * 8 + p * 2 + (m8 >> 1);
                    const uint32_t boff = (uint32_t)(kr * 256 + ((cc ^ (kr & 7)) << 4));
                    uint32_t bh0, bh1, bh2, bh3, bl0, bl1, bl2, bl3;
                    ldsm4t(bh0, bh1, bh2, bh3, smb + SM_HI(st) + boff);
                    ldsm4t(bl0, bl1, bl2, bl3, smb + SM_LO(st) + boff);
                    #pragma unroll
                    for (int mt = 0; mt < 2; mt++){
                        float* ca = cX[mt * 8 + 2 * p];
                        float* cb2 = cX[mt * 8 + 2 * p + 1];
                        mma16816(ca,  ah[mt][0], ah[mt][1], ah[mt][2], ah[mt][3], bh0, bh1);
                        mma16816(ca,  ah[mt][0], ah[mt][1], ah[mt][2], ah[mt][3], bl0, bl1);
                        mma16816(ca,  al[mt][0], al[mt][1], al[mt][2], al[mt][3], bh0, bh1);
                        mma16816(cb2, ah[mt][0], ah[mt][1], ah[mt][2], ah[mt][3], bh2, bh3);
                        mma16816(cb2, ah[mt][0], ah[mt][1], ah[mt][2], ah[mt][3], bl2, bl3);
                        mma16816(cb2, al[mt][0], al[mt][1], al[mt][2], al[mt][3], bh2, bh3);
                    }
                }
            }
        }

        // ---- fold x into fused accumulator: cT += (wx/den_row) * cX ----
        #pragma unroll
        for (int j = 0; j < 4; j++){
            den[j] += __shfl_xor_sync(0xffffffffu, den[j], 1);
            den[j] += __shfl_xor_sync(0xffffffffu, den[j], 2);
        }
        const float wx = fwv[x] * finv;
        #pragma unroll
        for (int mt = 0; mt < 2; mt++){
            float la = wx / den[2 * mt];
            float lb = wx / den[2 * mt + 1];
            #pragma unroll
            for (int nt = 0; nt < 8; nt++){
                int f = mt * 8 + nt;
                cT[f][0] = fmaf(la, cX[f][0], cT[f][0]);
                cT[f][1] = fmaf(la, cX[f][1], cT[f][1]);
                cT[f][2] = fmaf(lb, cX[f][2], cT[f][2]);
                cT[f][3] = fmaf(lb, cX[f][3], cT[f][3]);
            }
        }
    }

    // ---- epilogue ----
    #pragma unroll
    for (int mt = 0; mt < 2; mt++){
        int row = m0 + wm * 32 + mt * 16 + (lane >> 2);
        #pragma unroll
        for (int nt = 0; nt < 8; nt++){
            int col = wn * 64 + nt * 8 + (lane & 3) * 2;
            float* o = out + ((size_t)b * (NE * NP) + (size_t)e * NP + row) * ND + col;
            int f = mt * 8 + nt;
            float2 v0 = {cT[f][0], cT[f][1]};
            float2 v1 = {cT[f][2], cT[f][3]};
            *(float2*)o = v0;
            *(float2*)(o + 8 * ND) = v1;
        }
    }
}

// ---- host: replicate numpy route construction exactly ----
static void compute_routes(RoutesP* rp)
{
    float coords[NE];
    for (int i = 0; i < NE; i++){
        double xx = (double)i / 15.0;
        if (xx < 1e-6)       xx = 1e-6;
        if (xx > 1.0 - 1e-6) xx = 1.0 - 1e-6;
        double val = 0.0, f = 0.5;
        for (int d = 0; d < 8; d++){
            xx *= 3.0;
            int dig = (int)xx;
            xx -= (double)dig;
            if (dig == 2) val += f;
            f *= 0.5;
        }
        coords[i] = (float)val;
    }
    for (int i = 0; i < NE; i++){
        float dist[NE]; int idx[NE];
        for (int j = 0; j < NE; j++){ dist[j] = fabsf(coords[j] - coords[i]); idx[j] = j; }
        for (int a = 1; a < NE; a++){
            float dv = dist[a]; int iv = idx[a];
            int c = a - 1;
            while (c >= 0 && dist[c] > dv){
                dist[c + 1] = dist[c]; idx[c + 1] = idx[c]; c--;
            }
            dist[c + 1] = dv; idx[c + 1] = iv;
        }
        int r3[NW] = { idx[0], idx[1], idx[2] };
        for (int a = 0; a < NW; a++)
            for (int c = a + 1; c < NW; c++)
                if (r3[c] < r3[a]){ int t = r3[a]; r3[a] = r3[c]; r3[c] = t; }
        for (int w = 0; w < NW; w++) rp->ve[i][w] = r3[w];
    }
}

extern "C" void kernel_launch(void* const* d_in, const int* in_sizes, int n_in,
                              void* d_out, int out_size)
{
    (void)in_sizes; (void)n_in; (void)out_size;
    cudaFuncSetAttribute(cantor_attn_mma,
                         cudaFuncAttributeMaxDynamicSharedMemorySize, SMEM_TOTAL);

    RoutesP rp;
    compute_routes(&rp);

    // 1) V -> bf16 hi/lo planes (elementwise)
    const size_t nV = (size_t)NDIRS * NE * NB * NP * ND;   // 10,485,760
    vsplit_kernel<<<(unsigned)(nV / (256 * 4)), 256>>>((const float*)d_in[2]);

    // 2) fused attention, mma.sync bf16 3-term
    dim3 g2(NP / MT, NB, NE);   // (2, 4, 16) = 128 blocks
    cantor_attn_mma<<<g2, 256, SMEM_TOTAL>>>(
        (const float*)d_in[0],   // Q_aff
        (const float*)d_in[1],   // K_aff
        (const float*)d_in[3],   // betas
        (const float*)d_in[4],   // temperature
        (const float*)d_in[5],   // fusion_weights
        (float*)d_out, rp);
}

// round 6
// speedup vs baseline: 3.3181x; 1.0919x over previous
#include <cuda_runtime.h>
#include <cuda_bf16.h>
#include <math.h>
#include <stdint.h>

#define NDIRS 5
#define NE    16
#define NW    3
#define ND    128
#define NP    256
#define NB    4
#define WK    768
#define MT    128
#define KC    64
#define NCH   (WK/KC)     // 12 chunks per x
#define NG    (NDIRS*NCH) // 60 global chunks
#define NST   3
#define LOG2E 1.4426950408889634f

struct RoutesP { int ve[NE][NW]; };

// V split planes, [x][e][b][p][d], bf16 hi/lo (elementwise, same layout as V)
__device__ __align__(16) __nv_bfloat16 g_vh[(size_t)NDIRS*NE*NB*NP*ND];
__device__ __align__(16) __nv_bfloat16 g_vl[(size_t)NDIRS*NE*NB*NP*ND];

// ---------------- dynamic smem layout ----------------
// stage s: hi tile [KC][128] bf16 (16KB) + lo tile (16KB), XOR-swizzled 16B chunks
#define SM_HI(s)  ((s)*32768)
#define SM_LO(s)  ((s)*32768 + 16384)
#define SM_S      (NST*32768)          // f32[768]
#define SM_Q      (SM_S + 3072)        // f32[128]
#define SM_MX     (SM_Q + 512)         // f32[128]
#define SM_RED    (SM_MX + 512)        // f32[16]
#define SM_MM     (SM_RED + 64)        // f32[2]
#define SMEM_TOTAL (SM_MM + 64)        // ~100.1 KB

// ---------------- helpers ----------------
__device__ __forceinline__ uint32_t smem_u32(const void* p){
    uint32_t a;
    asm("{ .reg .u64 t; cvta.to.shared.u64 t, %1; cvt.u32.u64 %0, t; }" : "=r"(a) : "l"(p));
    return a;
}
__device__ __forceinline__ float ex2f(float x){
    float r; asm("ex2.approx.ftz.f32 %0, %1;" : "=f"(r) : "f"(x)); return r;
}
// bf16x2: low half = a, high half = b
__device__ __forceinline__ uint32_t pack_bf(float a, float b){
    uint32_t r;
    asm("cvt.rn.bf16x2.f32 %0, %1, %2;" : "=r"(r) : "f"(b), "f"(a));
    return r;
}
__device__ __forceinline__ void ldsm4t(uint32_t& r0, uint32_t& r1, uint32_t& r2, uint32_t& r3,
                                       uint32_t addr){
    asm volatile("ldmatrix.sync.aligned.m8n8.x4.trans.shared.b16 {%0,%1,%2,%3}, [%4];"
                 : "=r"(r0), "=r"(r1), "=r"(r2), "=r"(r3) : "r"(addr));
}
__device__ __forceinline__ void mma16816(float* c,
                                         uint32_t a0, uint32_t a1, uint32_t a2, uint32_t a3,
                                         uint32_t b0, uint32_t b1){
    asm volatile("mma.sync.aligned.m16n8k16.row.col.f32.bf16.bf16.f32 "
                 "{%0,%1,%2,%3}, {%4,%5,%6,%7}, {%8,%9}, {%0,%1,%2,%3};"
                 : "+f"(c[0]), "+f"(c[1]), "+f"(c[2]), "+f"(c[3])
                 : "r"(a0), "r"(a1), "r"(a2), "r"(a3), "r"(b0), "r"(b1));
}
__device__ __forceinline__ void cp16(uint32_t dst, const void* src){
    asm volatile("cp.async.cg.shared.global [%0], [%1], 16;" :: "r"(dst), "l"(src));
}
__device__ __forceinline__ void cp_commit(){ asm volatile("cp.async.commit_group;" ::: "memory"); }
template<int N> __device__ __forceinline__ void cp_wait(){
    asm volatile("cp.async.wait_group %0;" :: "n"(N) : "memory");
}

// stage a KC x 128 hi/lo chunk into smem stage st with 16B-chunk XOR swizzle
__device__ __forceinline__ void issue_chunk(uint32_t smb, int st,
                                            const __nv_bfloat16* __restrict__ srcH,
                                            const __nv_bfloat16* __restrict__ srcL,
                                            int tid){
    #pragma unroll
    for (int i = 0; i < 4; i++){
        int cid = tid + i * 256;              // 0..1023 16B chunks
        int row = cid >> 4, c = cid & 15;
        uint32_t soff = (uint32_t)(row * 256 + ((c ^ (row & 7)) << 4));
        cp16(smb + SM_HI(st) + soff, srcH + row * ND + c * 8);
        cp16(smb + SM_LO(st) + soff, srcL + row * ND + c * 8);
    }
}

// ---------------- pre-kernel: elementwise V -> bf16 hi/lo ----------------
__global__ __launch_bounds__(256)
void vsplit_kernel(const float* __restrict__ V){
    size_t i = ((size_t)blockIdx.x * 256 + threadIdx.x) * 4;
    float4 v = *(const float4*)(V + i);
    uint32_t h0 = pack_bf(v.x, v.y);
    uint32_t h1 = pack_bf(v.z, v.w);
    float fx = __uint_as_float(h0 << 16),        fy = __uint_as_float(h0 & 0xFFFF0000u);
    float fz = __uint_as_float(h1 << 16),        fw = __uint_as_float(h1 & 0xFFFF0000u);
    uint32_t l0 = pack_bf(v.x - fx, v.y - fy);
    uint32_t l1 = pack_bf(v.z - fz, v.w - fw);
    uint2 ph = {h0, h1}, pl = {l0, l1};
    *(uint2*)((char*)g_vh + i * 2) = ph;
    *(uint2*)((char*)g_vl + i * 2) = pl;
}

// ---------------- main kernel ----------------
__global__ __launch_bounds__(256, 1)
void cantor_attn_mma(const float* __restrict__ Q,
                     const float* __restrict__ Kf,
                     const float* __restrict__ betas,
                     const float* __restrict__ temp,
                     const float* __restrict__ fw,
                     float* __restrict__ out,
                     RoutesP rp)
{
    extern __shared__ char sm[];
    const uint32_t smb = smem_u32(sm);
    float* sS  = (float*)(sm + SM_S);
    float* sQ  = (float*)(sm + SM_Q);
    float* sMx = (float*)(sm + SM_MX);
    float* sRed= (float*)(sm + SM_RED);
    float* sMM = (float*)(sm + SM_MM);

    const int tid  = threadIdx.x;
    const int lane = tid & 31;
    const int wid  = tid >> 5;          // 8 warps, warp wid owns rows wid*16..+15
    const int e  = blockIdx.z;
    const int b  = blockIdx.y;
    const int m0 = blockIdx.x * MT;

    const float invtemp = 1.0f / (fabsf(temp[0]) + 1e-6f);

    // fusion softmax weights
    float fwv[NDIRS], fm = -1e30f;
    #pragma unroll
    for (int x = 0; x < NDIRS; x++){ fwv[x] = fw[x]; fm = fmaxf(fm, fwv[x]); }
    float fsum = 0.0f;
    #pragma unroll
    for (int x = 0; x < NDIRS; x++){ fwv[x] = __expf(fwv[x] - fm); fsum += fwv[x]; }
    const float finv = 1.0f / fsum;

    int   ve[NW]; float bfw[NW];
    #pragma unroll
    for (int w = 0; w < NW; w++){
        int r = rp.ve[e][w];
        ve[w] = r;
        float bf = (r == e) ? 1.0f : 1.0f / (1.0f + __expf(-betas[e * NE + r]));
        bfw[w] = bf * invtemp;
    }

    float cT[16][4];
    #pragma unroll
    for (int f = 0; f < 16; f++){
        cT[f][0] = 0.f; cT[f][1] = 0.f; cT[f][2] = 0.f; cT[f][3] = 0.f;
    }

    const int c0 = (lane & 3) * 2;
    const int rl = wid * 16 + (lane >> 2);   // thread rows rl, rl+8
    const int m8 = lane >> 3, w8 = lane & 7; // ldsm addressing

    // prefetch global chunks 0 and 1 (ve is x-independent: route depends only on e)
    {
        const size_t pb0 = (size_t)((0 * NE + ve[0]) * NB + b) * (NP * ND);
        issue_chunk(smb, 0, g_vh + pb0, g_vl + pb0, tid);
        cp_commit();
        const size_t pb1 = pb0 + (size_t)KC * ND;
        issue_chunk(smb, 1, g_vh + pb1, g_vl + pb1, tid);
        cp_commit();
    }

    for (int x = 0; x < NDIRS; x++){
        __syncthreads();   // previous x fully done with sS before rebuild

        // ---- prologue: s, q, minmax, mx ----
        #pragma unroll
        for (int i = 0; i < 3; i++){
            int idx = tid + i * 256;
            int w = idx >> 8, k = idx & 255;
            sS[idx] = Kf[(((x * NE + ve[w]) * NB + b) << 8) + k] * bfw[w];
        }
        if (tid < MT)
            sQ[tid] = Q[(((x * NE + e) * NB + b) << 8) + m0 + tid];
        __syncthreads();

        float lmax = -1e30f, lmin = 1e30f;
        #pragma unroll
        for (int i = 0; i < 3; i++){
            float v = sS[tid + i * 256];
            lmax = fmaxf(lmax, v); lmin = fminf(lmin, v);
        }
        #pragma unroll
        for (int off = 16; off; off >>= 1){
            lmax = fmaxf(lmax, __shfl_xor_sync(0xffffffffu, lmax, off));
            lmin = fminf(lmin, __shfl_xor_sync(0xffffffffu, lmin, off));
        }
        if (lane == 0){ sRed[wid] = lmax; sRed[8 + wid] = lmin; }
        __syncthreads();
        if (tid == 0){
            float a = -1e30f, c = 1e30f;
            #pragma unroll
            for (int i = 0; i < 8; i++){ a = fmaxf(a, sRed[i]); c = fminf(c, sRed[8 + i]); }
            sMM[0] = a; sMM[1] = c;
        }
        __syncthreads();
        if (tid < MT){
            float q = sQ[tid];
            sMx[tid] = fmaxf(q * sMM[0], q * sMM[1]);
        }
        __syncthreads();

        const float qa = sQ[rl] * LOG2E;
        const float qb = sQ[rl + 8] * LOG2E;
        const float ma = -sMx[rl] * LOG2E;
        const float mb = -sMx[rl + 8] * LOG2E;

        float cX[16][4];
        #pragma unroll
        for (int f = 0; f < 16; f++){
            cX[f][0] = 0.f; cX[f][1] = 0.f; cX[f][2] = 0.f; cX[f][3] = 0.f;
        }
        float den0 = 0.f, den1 = 0.f;

        // ---- chunk loop: 3-stage ring, one barrier per chunk ----
        for (int ch = 0; ch < NCH; ch++){
            const int g = x * NCH + ch;
            cp_wait<1>();
            __syncthreads();     // stage g%3 ready; stage (g+2)%3 == (g-1)%3 now free

            {
                const int g2 = g + 2;
                if (g2 < NG){
                    const int xg = g2 / NCH;
                    const int kt = (g2 % NCH) * KC;
                    const size_t pb = (size_t)((xg * NE + ve[kt >> 8]) * NB + b) * (NP * ND)
                                      + (size_t)(kt & 255) * ND;
                    issue_chunk(smb, g2 % NST, g_vh + pb, g_vl + pb, tid);
                }
                cp_commit();     // empty group near the end keeps counts uniform
            }

            const int st = g % NST;
            const int koff = ch * KC;

            #pragma unroll
            for (int k16 = 0; k16 < 4; k16++){
                const int kb = k16 * 16;

                // ---- A fragments (rows rl, rl+8): exp at frag coords, hi/lo split ----
                float sv0 = sS[koff + kb + c0];
                float sv1 = sS[koff + kb + c0 + 1];
                float sv2 = sS[koff + kb + c0 + 8];
                float sv3 = sS[koff + kb + c0 + 9];

                float ea0 = ex2f(fmaf(qa, sv0, ma));
                float ea1 = ex2f(fmaf(qa, sv1, ma));
                float ea2 = ex2f(fmaf(qa, sv2, ma));
                float ea3 = ex2f(fmaf(qa, sv3, ma));
                float eb0 = ex2f(fmaf(qb, sv0, mb));
                float eb1 = ex2f(fmaf(qb, sv1, mb));
                float eb2 = ex2f(fmaf(qb, sv2, mb));
                float eb3 = ex2f(fmaf(qb, sv3, mb));
                den0 += (ea0 + ea1) + (ea2 + ea3);
                den1 += (eb0 + eb1) + (eb2 + eb3);

                uint32_t h;
                uint32_t ah0, ah1, ah2, ah3, al0, al1, al2, al3;
                h = pack_bf(ea0, ea1); ah0 = h;
                al0 = pack_bf(ea0 - __uint_as_float(h << 16),
                              ea1 - __uint_as_float(h & 0xFFFF0000u));
                h = pack_bf(eb0, eb1); ah1 = h;
                al1 = pack_bf(eb0 - __uint_as_float(h << 16),
                              eb1 - __uint_as_float(h & 0xFFFF0000u));
                h = pack_bf(ea2, ea3); ah2 = h;
                al2 = pack_bf(ea2 - __uint_as_float(h << 16),
                              ea3 - __uint_as_float(h & 0xFFFF0000u));
                h = pack_bf(eb2, eb3); ah3 = h;
                al3 = pack_bf(eb2 - __uint_as_float(h << 16),
                              eb3 - __uint_as_float(h & 0xFFFF0000u));

                // ---- B fragments + MMA over all 8 n16 blocks ----
                const int kr = kb + (m8 & 1) * 8 + w8;
                #pragma unroll
                for (int nb = 0; nb < 8; nb++){
                    const int cc = nb * 2 + (m8 >> 1);
                    const uint32_t boff = (uint32_t)(kr * 256 + ((cc ^ (kr & 7)) << 4));
                    uint32_t bh0, bh1, bh2, bh3, bl0, bl1, bl2, bl3;
                    ldsm4t(bh0, bh1, bh2, bh3, smb + SM_HI(st) + boff);
                    ldsm4t(bl0, bl1, bl2, bl3, smb + SM_LO(st) + boff);
                    float* ca = cX[2 * nb];
                    float* cb = cX[2 * nb + 1];
                    mma16816(ca, ah0, ah1, ah2, ah3, bh0, bh1);
                    mma16816(cb, ah0, ah1, ah2, ah3, bh2, bh3);
                    mma16816(ca, ah0, ah1, ah2, ah3, bl0, bl1);
                    mma16816(cb, ah0, ah1, ah2, ah3, bl2, bl3);
                    mma16816(ca, al0, al1, al2, al3, bh0, bh1);
                    mma16816(cb, al0, al1, al2, al3, bh2, bh3);
                }
            }
        }

        // ---- fold x into fused accumulator: cT += (wx/den_row) * cX ----
        den0 += __shfl_xor_sync(0xffffffffu, den0, 1);
        den0 += __shfl_xor_sync(0xffffffffu, den0, 2);
        den1 += __shfl_xor_sync(0xffffffffu, den1, 1);
        den1 += __shfl_xor_sync(0xffffffffu, den1, 2);
        const float wx = fwv[x] * finv;
        const float la = wx / den0;
        const float lb = wx / den1;
        #pragma unroll
        for (int f = 0; f < 16; f++){
            cT[f][0] = fmaf(la, cX[f][0], cT[f][0]);
            cT[f][1] = fmaf(la, cX[f][1], cT[f][1]);
            cT[f][2] = fmaf(lb, cX[f][2], cT[f][2]);
            cT[f][3] = fmaf(lb, cX[f][3], cT[f][3]);
        }
    }

    // drain all outstanding async copies before CTA exit (tail groups are empty)
    cp_wait<0>();

    // ---- epilogue ----
    {
        const int row = m0 + rl;
        float* obase = out + ((size_t)b * (NE * NP) + (size_t)e * NP + row) * ND;
        #pragma unroll
        for (int f = 0; f < 16; f++){
            const int nb = f >> 1, t = f & 1;
            const int col = nb * 16 + t * 8 + (lane & 3) * 2;
            float2 v0 = {cT[f][0], cT[f][1]};
            float2 v1 = {cT[f][2], cT[f][3]};
            *(float2*)(obase + col) = v0;
            *(float2*)(obase + (size_t)8 * ND + col) = v1;
        }
    }
}

// ---- host: replicate numpy route construction exactly ----
static void compute_routes(RoutesP* rp)
{
    float coords[NE];
    for (int i = 0; i < NE; i++){
        double xx = (double)i / 15.0;
        if (xx < 1e-6)       xx = 1e-6;
        if (xx > 1.0 - 1e-6) xx = 1.0 - 1e-6;
        double val = 0.0, f = 0.5;
        for (int d = 0; d < 8; d++){
            xx *= 3.0;
            int dig = (int)xx;
            xx -= (double)dig;
            if (dig == 2) val += f;
            f *= 0.5;
        }
        coords[i] = (float)val;
    }
    for (int i = 0; i < NE; i++){
        float dist[NE]; int idx[NE];
        for (int j = 0; j < NE; j++){ dist[j] = fabsf(coords[j] - coords[i]); idx[j] = j; }
        for (int a = 1; a < NE; a++){
            float dv = dist[a]; int iv = idx[a];
            int c = a - 1;
            while (c >= 0 && dist[c] > dv){
                dist[c + 1] = dist[c]; idx[c + 1] = idx[c]; c--;
            }
            dist[c + 1] = dv; idx[c + 1] = iv;
        }
        int r3[NW] = { idx[0], idx[1], idx[2] };
        for (int a = 0; a < NW; a++)
            for (int c = a + 1; c < NW; c++)
                if (r3[c] < r3[a]){ int t = r3[a]; r3[a] = r3[c]; r3[c] = t; }
        for (int w = 0; w < NW; w++) rp->ve[i][w] = r3[w];
    }
}

extern "C" void kernel_launch(void* const* d_in, const int* in_sizes, int n_in,
                              void* d_out, int out_size)
{
    (void)in_sizes; (void)n_in; (void)out_size;
    cudaFuncSetAttribute(cantor_attn_mma,
                         cudaFuncAttributeMaxDynamicSharedMemorySize, SMEM_TOTAL);

    RoutesP rp;
    compute_routes(&rp);

    // 1) V -> bf16 hi/lo planes (elementwise)
    const size_t nV = (size_t)NDIRS * NE * NB * NP * ND;   // 10,485,760
    vsplit_kernel<<<(unsigned)(nV / (256 * 4)), 256>>>((const float*)d_in[2]);

    // 2) fused attention, mma.sync bf16 3-term
    dim3 g2(NP / MT, NB, NE);   // (2, 4, 16) = 128 blocks
    cantor_attn_mma<<<g2, 256, SMEM_TOTAL>>>(
        (const float*)d_in[0],   // Q_aff
        (const float*)d_in[1],   // K_aff
        (const float*)d_in[3],   // betas
        (const float*)d_in[4],   // temperature
        (const float*)d_in[5],   // fusion_weights
        (float*)d_out, rp);
}

// round 8
// speedup vs baseline: 4.5616x; 1.3748x over previous
#include <cuda_runtime.h>
#include <cuda_fp16.h>
#include <math.h>
#include <stdint.h>

#define NDIRS 5
#define NE    16
#define NW    3
#define ND    128
#define NP    256
#define NB    4
#define WK    768
#define MT    128
#define KC    64
#define NCH   (WK/KC)     // 12 chunks per x
#define NG    (NDIRS*NCH) // 60 global chunks
#define NST   3
#define LOG2E 1.4426950408889634f

struct RoutesP { int ve[NE][NW]; };

// V as fp16, [x][e][b][p][d] (elementwise convert, same layout as V)
__device__ __align__(16) __half g_v16[(size_t)NDIRS*NE*NB*NP*ND];

// ---------------- dynamic smem layout ----------------
// stage s: [KC][128] fp16 tile (16KB), XOR-swizzled 16B chunks
#define SM_V(s)   ((s)*16384)
#define SM_S      (NST*16384)          // f32[768]
#define SM_Q      (SM_S + 3072)        // f32[128]
#define SM_MX     (SM_Q + 512)         // f32[128]
#define SM_RED    (SM_MX + 512)        // f32[16]
#define SM_MM     (SM_RED + 64)        // f32[2]
#define SMEM_TOTAL (SM_MM + 64)        // ~53.4 KB

// ---------------- helpers ----------------
__device__ __forceinline__ uint32_t smem_u32(const void* p){
    uint32_t a;
    asm("{ .reg .u64 t; cvta.to.shared.u64 t, %1; cvt.u32.u64 %0, t; }" : "=r"(a) : "l"(p));
    return a;
}
__device__ __forceinline__ float ex2f(float x){
    float r; asm("ex2.approx.ftz.f32 %0, %1;" : "=f"(r) : "f"(x)); return r;
}
// pack two f32 -> f16x2 (lo=a, hi=b)
__device__ __forceinline__ uint32_t pack_h2(float a, float b){
    uint32_t r;
    asm("cvt.rn.f16x2.f32 %0, %2, %1;" : "=r"(r) : "f"(a), "f"(b));
    return r;
}
// unpack f16x2 -> two f32
__device__ __forceinline__ void unpack_h2(uint32_t h, float& a, float& b){
    asm("{ .reg .f16 x, y; mov.b32 {x, y}, %2; cvt.f32.f16 %0, x; cvt.f32.f16 %1, y; }"
        : "=f"(a), "=f"(b) : "r"(h));
}
__device__ __forceinline__ void ldsm4t(uint32_t& r0, uint32_t& r1, uint32_t& r2, uint32_t& r3,
                                       uint32_t addr){
    asm volatile("ldmatrix.sync.aligned.m8n8.x4.trans.shared.b16 {%0,%1,%2,%3}, [%4];"
                 : "=r"(r0), "=r"(r1), "=r"(r2), "=r"(r3) : "r"(addr));
}
__device__ __forceinline__ void mma16816(float* c,
                                         uint32_t a0, uint32_t a1, uint32_t a2, uint32_t a3,
                                         uint32_t b0, uint32_t b1){
    asm volatile("mma.sync.aligned.m16n8k16.row.col.f32.f16.f16.f32 "
                 "{%0,%1,%2,%3}, {%4,%5,%6,%7}, {%8,%9}, {%0,%1,%2,%3};"
                 : "+f"(c[0]), "+f"(c[1]), "+f"(c[2]), "+f"(c[3])
                 : "r"(a0), "r"(a1), "r"(a2), "r"(a3), "r"(b0), "r"(b1));
}
__device__ __forceinline__ void cp16(uint32_t dst, const void* src){
    asm volatile("cp.async.cg.shared.global [%0], [%1], 16;" :: "r"(dst), "l"(src));
}
__device__ __forceinline__ void cp_commit(){ asm volatile("cp.async.commit_group;" ::: "memory"); }
template<int N> __device__ __forceinline__ void cp_wait(){
    asm volatile("cp.async.wait_group %0;" :: "n"(N) : "memory");
}

// stage a KC x 128 fp16 chunk into smem stage st with 16B-chunk XOR swizzle
__device__ __forceinline__ void issue_chunk(uint32_t smb, int st,
                                            const __half* __restrict__ src,
                                            int tid){
    #pragma unroll
    for (int i = 0; i < 4; i++){
        int cid = tid + i * 256;              // 0..1023 16B chunks
        int row = cid >> 4, c = cid & 15;
        uint32_t soff = (uint32_t)(row * 256 + ((c ^ (row & 7)) << 4));
        cp16(smb + SM_V(st) + soff, src + row * ND + c * 8);
    }
}

// ---------------- pre-kernel: elementwise V -> fp16 ----------------
__global__ __launch_bounds__(256)
void vsplit_kernel(const float* __restrict__ V){
    size_t i = ((size_t)blockIdx.x * 256 + threadIdx.x) * 8;
    float4 v0 = *(const float4*)(V + i);
    float4 v1 = *(const float4*)(V + i + 4);
    uint4 o;
    o.x = pack_h2(v0.x, v0.y);
    o.y = pack_h2(v0.z, v0.w);
    o.z = pack_h2(v1.x, v1.y);
    o.w = pack_h2(v1.z, v1.w);
    *(uint4*)((char*)g_v16 + i * 2) = o;
}

// ---------------- main kernel ----------------
__global__ __launch_bounds__(256, 1)
void cantor_attn_mma(const float* __restrict__ Q,
                     const float* __restrict__ Kf,
                     const float* __restrict__ betas,
                     const float* __restrict__ temp,
                     const float* __restrict__ fw,
                     float* __restrict__ out,
                     RoutesP rp)
{
    extern __shared__ char sm[];
    const uint32_t smb = smem_u32(sm);
    float* sS  = (float*)(sm + SM_S);
    float* sQ  = (float*)(sm + SM_Q);
    float* sMx = (float*)(sm + SM_MX);
    float* sRed= (float*)(sm + SM_RED);
    float* sMM = (float*)(sm + SM_MM);

    const int tid  = threadIdx.x;
    const int lane = tid & 31;
    const int wid  = tid >> 5;          // 8 warps, warp wid owns rows wid*16..+15
    const int e  = blockIdx.z;
    const int b  = blockIdx.y;
    const int m0 = blockIdx.x * MT;

    const float invtemp = 1.0f / (fabsf(temp[0]) + 1e-6f);

    // fusion softmax weights
    float fwv[NDIRS], fm = -1e30f;
    #pragma unroll
    for (int x = 0; x < NDIRS; x++){ fwv[x] = fw[x]; fm = fmaxf(fm, fwv[x]); }
    float fsum = 0.0f;
    #pragma unroll
    for (int x = 0; x < NDIRS; x++){ fwv[x] = __expf(fwv[x] - fm); fsum += fwv[x]; }
    const float finv = 1.0f / fsum;

    int   ve[NW]; float bfw[NW];
    #pragma unroll
    for (int w = 0; w < NW; w++){
        int r = rp.ve[e][w];
        ve[w] = r;
        float bf = (r == e) ? 1.0f : 1.0f / (1.0f + __expf(-betas[e * NE + r]));
        bfw[w] = bf * invtemp;
    }

    float cT[16][4];
    #pragma unroll
    for (int f = 0; f < 16; f++){
        cT[f][0] = 0.f; cT[f][1] = 0.f; cT[f][2] = 0.f; cT[f][3] = 0.f;
    }

    const int c0 = (lane & 3) * 2;
    const int rl = wid * 16 + (lane >> 2);   // thread rows rl, rl+8
    const int m8 = lane >> 3, w8 = lane & 7; // ldsm addressing

    // prefetch global chunks 0 and 1 (ve is x-independent)
    {
        const size_t pb0 = (size_t)((0 * NE + ve[0]) * NB + b) * (NP * ND);
        issue_chunk(smb, 0, g_v16 + pb0, tid);
        cp_commit();
        issue_chunk(smb, 1, g_v16 + pb0 + (size_t)KC * ND, tid);
        cp_commit();
    }

    for (int x = 0; x < NDIRS; x++){
        __syncthreads();   // previous x fully done with sS before rebuild

        // ---- prologue: s, q, minmax, mx ----
        #pragma unroll
        for (int i = 0; i < 3; i++){
            int idx = tid + i * 256;
            int w = idx >> 8, k = idx & 255;
            sS[idx] = Kf[(((x * NE + ve[w]) * NB + b) << 8) + k] * bfw[w];
        }
        if (tid < MT)
            sQ[tid] = Q[(((x * NE + e) * NB + b) << 8) + m0 + tid];
        __syncthreads();

        float lmax = -1e30f, lmin = 1e30f;
        #pragma unroll
        for (int i = 0; i < 3; i++){
            float v = sS[tid + i * 256];
            lmax = fmaxf(lmax, v); lmin = fminf(lmin, v);
        }
        #pragma unroll
        for (int off = 16; off; off >>= 1){
            lmax = fmaxf(lmax, __shfl_xor_sync(0xffffffffu, lmax, off));
            lmin = fminf(lmin, __shfl_xor_sync(0xffffffffu, lmin, off));
        }
        if (lane == 0){ sRed[wid] = lmax; sRed[8 + wid] = lmin; }
        __syncthreads();
        if (tid == 0){
            float a = -1e30f, c = 1e30f;
            #pragma unroll
            for (int i = 0; i < 8; i++){ a = fmaxf(a, sRed[i]); c = fminf(c, sRed[8 + i]); }
            sMM[0] = a; sMM[1] = c;
        }
        __syncthreads();
        if (tid < MT){
            float q = sQ[tid];
            sMx[tid] = fmaxf(q * sMM[0], q * sMM[1]);
        }
        __syncthreads();

        const float qa = sQ[rl] * LOG2E;
        const float qb = sQ[rl + 8] * LOG2E;
        const float ma = -sMx[rl] * LOG2E;
        const float mb = -sMx[rl + 8] * LOG2E;

        float cX[16][4];
        #pragma unroll
        for (int f = 0; f < 16; f++){
            cX[f][0] = 0.f; cX[f][1] = 0.f; cX[f][2] = 0.f; cX[f][3] = 0.f;
        }
        float den0 = 0.f, den1 = 0.f;

        // ---- chunk loop: 3-stage ring, one barrier per chunk ----
        for (int ch = 0; ch < NCH; ch++){
            const int g = x * NCH + ch;
            cp_wait<1>();
            __syncthreads();     // stage g%3 ready; stage (g+2)%3 now free

            {
                const int g2 = g + 2;
                if (g2 < NG){
                    const int xg = g2 / NCH;
                    const int kt = (g2 % NCH) * KC;
                    const size_t pb = (size_t)((xg * NE + ve[kt >> 8]) * NB + b) * (NP * ND)
                                      + (size_t)(kt & 255) * ND;
                    issue_chunk(smb, g2 % NST, g_v16 + pb, tid);
                }
                cp_commit();     // empty group near the end keeps counts uniform
            }

            const int st = g % NST;
            const int koff = ch * KC;

            #pragma unroll
            for (int k16 = 0; k16 < 4; k16++){
                const int kb = k16 * 16;

                // ---- A fragments (rows rl, rl+8): exp, fp16 hi/lo split ----
                float sv0 = sS[koff + kb + c0];
                float sv1 = sS[koff + kb + c0 + 1];
                float sv2 = sS[koff + kb + c0 + 8];
                float sv3 = sS[koff + kb + c0 + 9];

                float ea0 = ex2f(fmaf(qa, sv0, ma));
                float ea1 = ex2f(fmaf(qa, sv1, ma));
                float ea2 = ex2f(fmaf(qa, sv2, ma));
                float ea3 = ex2f(fmaf(qa, sv3, ma));
                float eb0 = ex2f(fmaf(qb, sv0, mb));
                float eb1 = ex2f(fmaf(qb, sv1, mb));
                float eb2 = ex2f(fmaf(qb, sv2, mb));
                float eb3 = ex2f(fmaf(qb, sv3, mb));
                den0 += (ea0 + ea1) + (ea2 + ea3);
                den1 += (eb0 + eb1) + (eb2 + eb3);

                float t0, t1;
                uint32_t ah0, ah1, ah2, ah3, al0, al1, al2, al3;
                ah0 = pack_h2(ea0, ea1); unpack_h2(ah0, t0, t1);
                al0 = pack_h2(ea0 - t0, ea1 - t1);
                ah1 = pack_h2(eb0, eb1); unpack_h2(ah1, t0, t1);
                al1 = pack_h2(eb0 - t0, eb1 - t1);
                ah2 = pack_h2(ea2, ea3); unpack_h2(ah2, t0, t1);
                al2 = pack_h2(ea2 - t0, ea3 - t1);
                ah3 = pack_h2(eb2, eb3); unpack_h2(ah3, t0, t1);
                al3 = pack_h2(eb2 - t0, eb3 - t1);

                // ---- B fragments + MMA over all 8 n16 blocks (single fp16 plane) ----
                const int kr = kb + (m8 & 1) * 8 + w8;
                #pragma unroll
                for (int nb = 0; nb < 8; nb++){
                    const int cc = nb * 2 + (m8 >> 1);
                    const uint32_t boff = (uint32_t)(kr * 256 + ((cc ^ (kr & 7)) << 4));
                    uint32_t b0, b1, b2, b3;
                    ldsm4t(b0, b1, b2, b3, smb + SM_V(st) + boff);
                    float* ca = cX[2 * nb];
                    float* cb = cX[2 * nb + 1];
                    mma16816(ca, ah0, ah1, ah2, ah3, b0, b1);
                    mma16816(cb, ah0, ah1, ah2, ah3, b2, b3);
                    mma16816(ca, al0, al1, al2, al3, b0, b1);
                    mma16816(cb, al0, al1, al2, al3, b2, b3);
                }
            }
        }

        // ---- fold x into fused accumulator: cT += (wx/den_row) * cX ----
        den0 += __shfl_xor_sync(0xffffffffu, den0, 1);
        den0 += __shfl_xor_sync(0xffffffffu, den0, 2);
        den1 += __shfl_xor_sync(0xffffffffu, den1, 1);
        den1 += __shfl_xor_sync(0xffffffffu, den1, 2);
        const float wx = fwv[x] * finv;
        const float la = wx / den0;
        const float lb = wx / den1;
        #pragma unroll
        for (int f = 0; f < 16; f++){
            cT[f][0] = fmaf(la, cX[f][0], cT[f][0]);
            cT[f][1] = fmaf(la, cX[f][1], cT[f][1]);
            cT[f][2] = fmaf(lb, cX[f][2], cT[f][2]);
            cT[f][3] = fmaf(lb, cX[f][3], cT[f][3]);
        }
    }

    // drain outstanding async copies before CTA exit (tail groups are empty)
    cp_wait<0>();

    // ---- epilogue ----
    {
        const int row = m0 + rl;
        float* obase = out + ((size_t)b * (NE * NP) + (size_t)e * NP + row) * ND;
        #pragma unroll
        for (int f = 0; f < 16; f++){
            const int nb = f >> 1, t = f & 1;
            const int col = nb * 16 + t * 8 + (lane & 3) * 2;
            float2 v0 = {cT[f][0], cT[f][1]};
            float2 v1 = {cT[f][2], cT[f][3]};
            *(float2*)(obase + col) = v0;
            *(float2*)(obase + (size_t)8 * ND + col) = v1;
        }
    }
}

// ---- host: replicate numpy route construction exactly ----
static void compute_routes(RoutesP* rp)
{
    float coords[NE];
    for (int i = 0; i < NE; i++){
        double xx = (double)i / 15.0;
        if (xx < 1e-6)       xx = 1e-6;
        if (xx > 1.0 - 1e-6) xx = 1.0 - 1e-6;
        double val = 0.0, f = 0.5;
        for (int d = 0; d < 8; d++){
            xx *= 3.0;
            int dig = (int)xx;
            xx -= (double)dig;
            if (dig == 2) val += f;
            f *= 0.5;
        }
        coords[i] = (float)val;
    }
    for (int i = 0; i < NE; i++){
        float dist[NE]; int idx[NE];
        for (int j = 0; j < NE; j++){ dist[j] = fabsf(coords[j] - coords[i]); idx[j] = j; }
        for (int a = 1; a < NE; a++){
            float dv = dist[a]; int iv = idx[a];
            int c = a - 1;
            while (c >= 0 && dist[c] > dv){
                dist[c + 1] = dist[c]; idx[c + 1] = idx[c]; c--;
            }
            dist[c + 1] = dv; idx[c + 1] = iv;
        }
        int r3[NW] = { idx[0], idx[1], idx[2] };
        for (int a = 0; a < NW; a++)
            for (int c = a + 1; c < NW; c++)
                if (r3[c] < r3[a]){ int t = r3[a]; r3[a] = r3[c]; r3[c] = t; }
        for (int w = 0; w < NW; w++) rp->ve[i][w] = r3[w];
    }
}

extern "C" void kernel_launch(void* const* d_in, const int* in_sizes, int n_in,
                              void* d_out, int out_size)
{
    (void)in_sizes; (void)n_in; (void)out_size;
    cudaFuncSetAttribute(cantor_attn_mma,
                         cudaFuncAttributeMaxDynamicSharedMemorySize, SMEM_TOTAL);

    RoutesP rp;
    compute_routes(&rp);

    // 1) V -> fp16 plane (elementwise)
    const size_t nV = (size_t)NDIRS * NE * NB * NP * ND;   // 10,485,760
    vsplit_kernel<<<(unsigned)(nV / (256 * 8)), 256>>>((const float*)d_in[2]);

    // 2) fused attention, mma.sync fp16 2-term (A hi/lo, B single)
    dim3 g2(NP / MT, NB, NE);   // (2, 4, 16) = 128 blocks
    cantor_attn_mma<<<g2, 256, SMEM_TOTAL>>>(
        (const float*)d_in[0],   // Q_aff
        (const float*)d_in[1],   // K_aff
        (const float*)d_in[3],   // betas
        (const float*)d_in[4],   // temperature
        (const float*)d_in[5],   // fusion_weights
        (float*)d_out, rp);
}

// round 9
// speedup vs baseline: 7.1825x; 1.5745x over previous
#include <cuda_runtime.h>
#include <cuda_fp16.h>
#include <math.h>
#include <stdint.h>

#define NDIRS 5
#define NE    16
#define NW    3
#define ND    128
#define NP    256
#define NB    4
#define WK    768
#define MT    128
#define KC    64
#define NCH   (WK/KC)     // 12 chunks per x
#define NG    (NDIRS*NCH) // 60 global chunks
#define NST   3
#define LOG2E 1.4426950408889634f

struct RoutesP { int ve[NE][NW]; };

// V as fp16, [x][e][b][p][d] (elementwise convert, same layout as V)
__device__ __align__(16) __half g_v16[(size_t)NDIRS*NE*NB*NP*ND];

// ---------------- dynamic smem layout ----------------
// stage s: [KC][128] fp16 tile (16KB), XOR-swizzled 16B chunks
#define SM_V(s)   ((s)*16384)
#define SM_S      (NST*16384)          // f32[768]
#define SM_Q      (SM_S + 3072)        // f32[128]
#define SM_MX     (SM_Q + 512)         // f32[128]
#define SM_RED    (SM_MX + 512)        // f32[16]
#define SM_MM     (SM_RED + 64)        // f32[2]
#define SMEM_TOTAL (SM_MM + 64)        // ~53.4 KB

// ---------------- helpers ----------------
__device__ __forceinline__ uint32_t smem_u32(const void* p){
    uint32_t a;
    asm("{ .reg .u64 t; cvta.to.shared.u64 t, %1; cvt.u32.u64 %0, t; }" : "=r"(a) : "l"(p));
    return a;
}
__device__ __forceinline__ float ex2f(float x){
    float r; asm("ex2.approx.ftz.f32 %0, %1;" : "=f"(r) : "f"(x)); return r;
}
// pack two f32 -> f16x2 (lo=a, hi=b)
__device__ __forceinline__ uint32_t pack_h2(float a, float b){
    uint32_t r;
    asm("cvt.rn.f16x2.f32 %0, %2, %1;" : "=r"(r) : "f"(a), "f"(b));
    return r;
}
__device__ __forceinline__ void ldsm4t(uint32_t& r0, uint32_t& r1, uint32_t& r2, uint32_t& r3,
                                       uint32_t addr){
    asm volatile("ldmatrix.sync.aligned.m8n8.x4.trans.shared.b16 {%0,%1,%2,%3}, [%4];"
                 : "=r"(r0), "=r"(r1), "=r"(r2), "=r"(r3) : "r"(addr));
}
__device__ __forceinline__ void mma16816(float* c,
                                         uint32_t a0, uint32_t a1, uint32_t a2, uint32_t a3,
                                         uint32_t b0, uint32_t b1){
    asm volatile("mma.sync.aligned.m16n8k16.row.col.f32.f16.f16.f32 "
                 "{%0,%1,%2,%3}, {%4,%5,%6,%7}, {%8,%9}, {%0,%1,%2,%3};"
                 : "+f"(c[0]), "+f"(c[1]), "+f"(c[2]), "+f"(c[3])
                 : "r"(a0), "r"(a1), "r"(a2), "r"(a3), "r"(b0), "r"(b1));
}
__device__ __forceinline__ void cp16(uint32_t dst, const void* src){
    asm volatile("cp.async.cg.shared.global [%0], [%1], 16;" :: "r"(dst), "l"(src));
}
__device__ __forceinline__ void cp_commit(){ asm volatile("cp.async.commit_group;" ::: "memory"); }
template<int N> __device__ __forceinline__ void cp_wait(){
    asm volatile("cp.async.wait_group %0;" :: "n"(N) : "memory");
}

// stage a KC x 128 fp16 chunk into smem stage st with 16B-chunk XOR swizzle
__device__ __forceinline__ void issue_chunk(uint32_t smb, int st,
                                            const __half* __restrict__ src,
                                            int tid){
    #pragma unroll
    for (int i = 0; i < 4; i++){
        int cid = tid + i * 256;              // 0..1023 16B chunks
        int row = cid >> 4, c = cid & 15;
        uint32_t soff = (uint32_t)(row * 256 + ((c ^ (row & 7)) << 4));
        cp16(smb + SM_V(st) + soff, src + row * ND + c * 8);
    }
}

// ---------------- pre-kernel: elementwise V -> fp16 ----------------
__global__ __launch_bounds__(256)
void vsplit_kernel(const float* __restrict__ V){
    size_t i = ((size_t)blockIdx.x * 256 + threadIdx.x) * 8;
    float4 v0 = *(const float4*)(V + i);
    float4 v1 = *(const float4*)(V + i + 4);
    uint4 o;
    o.x = pack_h2(v0.x, v0.y);
    o.y = pack_h2(v0.z, v0.w);
    o.z = pack_h2(v1.x, v1.y);
    o.w = pack_h2(v1.z, v1.w);
    *(uint4*)((char*)g_v16 + i * 2) = o;
}

// ---------------- main kernel ----------------
__global__ __launch_bounds__(256, 1)
void cantor_attn_mma(const float* __restrict__ Q,
                     const float* __restrict__ Kf,
                     const float* __restrict__ betas,
                     const float* __restrict__ temp,
                     const float* __restrict__ fw,
                     float* __restrict__ out,
                     RoutesP rp)
{
    extern __shared__ char sm[];
    const uint32_t smb = smem_u32(sm);
    float* sS  = (float*)(sm + SM_S);
    float* sQ  = (float*)(sm + SM_Q);
    float* sMx = (float*)(sm + SM_MX);
    float* sRed= (float*)(sm + SM_RED);
    float* sMM = (float*)(sm + SM_MM);

    const int tid  = threadIdx.x;
    const int lane = tid & 31;
    const int wid  = tid >> 5;          // 8 warps, warp wid owns rows wid*16..+15
    const int e  = blockIdx.z;
    const int b  = blockIdx.y;
    const int m0 = blockIdx.x * MT;

    const float invtemp = 1.0f / (fabsf(temp[0]) + 1e-6f);

    // fusion softmax weights
    float fwv[NDIRS], fm = -1e30f;
    #pragma unroll
    for (int x = 0; x < NDIRS; x++){ fwv[x] = fw[x]; fm = fmaxf(fm, fwv[x]); }
    float fsum = 0.0f;
    #pragma unroll
    for (int x = 0; x < NDIRS; x++){ fwv[x] = __expf(fwv[x] - fm); fsum += fwv[x]; }
    const float finv = 1.0f / fsum;

    int   ve[NW]; float bfw[NW];
    #pragma unroll
    for (int w = 0; w < NW; w++){
        int r = rp.ve[e][w];
        ve[w] = r;
        float bf = (r == e) ? 1.0f : 1.0f / (1.0f + __expf(-betas[e * NE + r]));
        bfw[w] = bf * invtemp;
    }

    float cT[16][4];
    #pragma unroll
    for (int f = 0; f < 16; f++){
        cT[f][0] = 0.f; cT[f][1] = 0.f; cT[f][2] = 0.f; cT[f][3] = 0.f;
    }

    const int c0 = (lane & 3) * 2;
    const int rl = wid * 16 + (lane >> 2);   // thread rows rl, rl+8
    const int m8 = lane >> 3, w8 = lane & 7; // ldsm addressing

    // prefetch global chunks 0 and 1 (ve is x-independent)
    {
        const size_t pb0 = (size_t)((0 * NE + ve[0]) * NB + b) * (NP * ND);
        issue_chunk(smb, 0, g_v16 + pb0, tid);
        cp_commit();
        issue_chunk(smb, 1, g_v16 + pb0 + (size_t)KC * ND, tid);
        cp_commit();
    }

    for (int x = 0; x < NDIRS; x++){
        __syncthreads();   // previous x fully done with sS before rebuild

        // ---- prologue: s, q, minmax, mx ----
        #pragma unroll
        for (int i = 0; i < 3; i++){
            int idx = tid + i * 256;
            int w = idx >> 8, k = idx & 255;
            sS[idx] = Kf[(((x * NE + ve[w]) * NB + b) << 8) + k] * bfw[w];
        }
        if (tid < MT)
            sQ[tid] = Q[(((x * NE + e) * NB + b) << 8) + m0 + tid];
        __syncthreads();

        float lmax = -1e30f, lmin = 1e30f;
        #pragma unroll
        for (int i = 0; i < 3; i++){
            float v = sS[tid + i * 256];
            lmax = fmaxf(lmax, v); lmin = fminf(lmin, v);
        }
        #pragma unroll
        for (int off = 16; off; off >>= 1){
            lmax = fmaxf(lmax, __shfl_xor_sync(0xffffffffu, lmax, off));
            lmin = fminf(lmin, __shfl_xor_sync(0xffffffffu, lmin, off));
        }
        if (lane == 0){ sRed[wid] = lmax; sRed[8 + wid] = lmin; }
        __syncthreads();
        if (tid == 0){
            float a = -1e30f, c = 1e30f;
            #pragma unroll
            for (int i = 0; i < 8; i++){ a = fmaxf(a, sRed[i]); c = fminf(c, sRed[8 + i]); }
            sMM[0] = a; sMM[1] = c;
        }
        __syncthreads();
        if (tid < MT){
            float q = sQ[tid];
            sMx[tid] = fmaxf(q * sMM[0], q * sMM[1]);
        }
        __syncthreads();

        const float qa = sQ[rl] * LOG2E;
        const float qb = sQ[rl + 8] * LOG2E;
        const float ma = -sMx[rl] * LOG2E;
        const float mb = -sMx[rl + 8] * LOG2E;

        float cX[16][4];
        #pragma unroll
        for (int f = 0; f < 16; f++){
            cX[f][0] = 0.f; cX[f][1] = 0.f; cX[f][2] = 0.f; cX[f][3] = 0.f;
        }
        float den0 = 0.f, den1 = 0.f;

        // ---- chunk loop: 3-stage ring, one barrier per chunk ----
        for (int ch = 0; ch < NCH; ch++){
            const int g = x * NCH + ch;
            cp_wait<1>();
            __syncthreads();     // stage g%3 ready; stage (g+2)%3 now free

            {
                const int g2 = g + 2;
                if (g2 < NG){
                    const int xg = g2 / NCH;
                    const int kt = (g2 % NCH) * KC;
                    const size_t pb = (size_t)((xg * NE + ve[kt >> 8]) * NB + b) * (NP * ND)
                                      + (size_t)(kt & 255) * ND;
                    issue_chunk(smb, g2 % NST, g_v16 + pb, tid);
                }
                cp_commit();     // empty group near the end keeps counts uniform
            }

            const int st = g % NST;
            const int koff = ch * KC;

            #pragma unroll
            for (int k16 = 0; k16 < 4; k16++){
                const int kb = k16 * 16;

                // ---- A fragments (rows rl, rl+8): exp -> fp16 (1-term) ----
                float sv0 = sS[koff + kb + c0];
                float sv1 = sS[koff + kb + c0 + 1];
                float sv2 = sS[koff + kb + c0 + 8];
                float sv3 = sS[koff + kb + c0 + 9];

                float ea0 = ex2f(fmaf(qa, sv0, ma));
                float ea1 = ex2f(fmaf(qa, sv1, ma));
                float ea2 = ex2f(fmaf(qa, sv2, ma));
                float ea3 = ex2f(fmaf(qa, sv3, ma));
                float eb0 = ex2f(fmaf(qb, sv0, mb));
                float eb1 = ex2f(fmaf(qb, sv1, mb));
                float eb2 = ex2f(fmaf(qb, sv2, mb));
                float eb3 = ex2f(fmaf(qb, sv3, mb));
                den0 += (ea0 + ea1) + (ea2 + ea3);
                den1 += (eb0 + eb1) + (eb2 + eb3);

                uint32_t ah0 = pack_h2(ea0, ea1);
                uint32_t ah1 = pack_h2(eb0, eb1);
                uint32_t ah2 = pack_h2(ea2, ea3);
                uint32_t ah3 = pack_h2(eb2, eb3);

                // ---- B fragments + MMA over all 8 n16 blocks (single fp16 plane) ----
                const int kr = kb + (m8 & 1) * 8 + w8;
                #pragma unroll
                for (int nb = 0; nb < 8; nb++){
                    const int cc = nb * 2 + (m8 >> 1);
                    const uint32_t boff = (uint32_t)(kr * 256 + ((cc ^ (kr & 7)) << 4));
                    uint32_t b0, b1, b2, b3;
                    ldsm4t(b0, b1, b2, b3, smb + SM_V(st) + boff);
                    mma16816(cX[2 * nb],     ah0, ah1, ah2, ah3, b0, b1);
                    mma16816(cX[2 * nb + 1], ah0, ah1, ah2, ah3, b2, b3);
                }
            }
        }

        // ---- fold x into fused accumulator: cT += (wx/den_row) * cX ----
        den0 += __shfl_xor_sync(0xffffffffu, den0, 1);
        den0 += __shfl_xor_sync(0xffffffffu, den0, 2);
        den1 += __shfl_xor_sync(0xffffffffu, den1, 1);
        den1 += __shfl_xor_sync(0xffffffffu, den1, 2);
        const float wx = fwv[x] * finv;
        const float la = wx / den0;
        const float lb = wx / den1;
        #pragma unroll
        for (int f = 0; f < 16; f++){
            cT[f][0] = fmaf(la, cX[f][0], cT[f][0]);
            cT[f][1] = fmaf(la, cX[f][1], cT[f][1]);
            cT[f][2] = fmaf(lb, cX[f][2], cT[f][2]);
            cT[f][3] = fmaf(lb, cX[f][3], cT[f][3]);
        }
    }

    // drain outstanding async copies before CTA exit (tail groups are empty)
    cp_wait<0>();

    // ---- epilogue ----
    {
        const int row = m0 + rl;
        float* obase = out + ((size_t)b * (NE * NP) + (size_t)e * NP + row) * ND;
        #pragma unroll
        for (int f = 0; f < 16; f++){
            const int nb = f >> 1, t = f & 1;
            const int col = nb * 16 + t * 8 + (lane & 3) * 2;
            float2 v0 = {cT[f][0], cT[f][1]};
            float2 v1 = {cT[f][2], cT[f][3]};
            *(float2*)(obase + col) = v0;
            *(float2*)(obase + (size_t)8 * ND + col) = v1;
        }
    }
}

// ---- host: replicate numpy route construction exactly ----
static void compute_routes(RoutesP* rp)
{
    float coords[NE];
    for (int i = 0; i < NE; i++){
        double xx = (double)i / 15.0;
        if (xx < 1e-6)       xx = 1e-6;
        if (xx > 1.0 - 1e-6) xx = 1.0 - 1e-6;
        double val = 0.0, f = 0.5;
        for (int d = 0; d < 8; d++){
            xx *= 3.0;
            int dig = (int)xx;
            xx -= (double)dig;
            if (dig == 2) val += f;
            f *= 0.5;
        }
        coords[i] = (float)val;
    }
    for (int i = 0; i < NE; i++){
        float dist[NE]; int idx[NE];
        for (int j = 0; j < NE; j++){ dist[j] = fabsf(coords[j] - coords[i]); idx[j] = j; }
        for (int a = 1; a < NE; a++){
            float dv = dist[a]; int iv = idx[a];
            int c = a - 1;
            while (c >= 0 && dist[c] > dv){
                dist[c + 1] = dist[c]; idx[c + 1] = idx[c]; c--;
            }
            dist[c + 1] = dv; idx[c + 1] = iv;
        }
        int r3[NW] = { idx[0], idx[1], idx[2] };
        for (int a = 0; a < NW; a++)
            for (int c = a + 1; c < NW; c++)
                if (r3[c] < r3[a]){ int t = r3[a]; r3[a] = r3[c]; r3[c] = t; }
        for (int w = 0; w < NW; w++) rp->ve[i][w] = r3[w];
    }
}

extern "C" void kernel_launch(void* const* d_in, const int* in_sizes, int n_in,
                              void* d_out, int out_size)
{
    (void)in_sizes; (void)n_in; (void)out_size;
    cudaFuncSetAttribute(cantor_attn_mma,
                         cudaFuncAttributeMaxDynamicSharedMemorySize, SMEM_TOTAL);

    RoutesP rp;
    compute_routes(&rp);

    // 1) V -> fp16 plane (elementwise)
    const size_t nV = (size_t)NDIRS * NE * NB * NP * ND;   // 10,485,760
    vsplit_kernel<<<(unsigned)(nV / (256 * 8)), 256>>>((const float*)d_in[2]);

    // 2) fused attention, mma.sync fp16 1-term
    dim3 g2(NP / MT, NB, NE);   // (2, 4, 16) = 128 blocks
    cantor_attn_mma<<<g2, 256, SMEM_TOTAL>>>(
        (const float*)d_in[0],   // Q_aff
        (const float*)d_in[1],   // K_aff
        (const float*)d_in[3],   // betas
        (const float*)d_in[4],   // temperature
        (const float*)d_in[5],   // fusion_weights
        (float*)d_out, rp);
}